// round 14
// baseline (speedup 1.0000x reference)
#include <cuda_runtime.h>
#include <cstdint>

// PKNeuralODE: 65536 trajectories, 2->64->64->2 ReLU MLP dynamics.
// One Heun step (h=24) per segment: k1=f(y), k2=f(y+h k1) (end slope for
// cubic Hermite dense output), y1 = y + h/2(k1+k2). 8 MLP evals total.
// Layer 2 via mma.sync m16n8k16 bf16, nt-outer.
// THIS ROUND: 16 traj/warp -> 4096 warps (28/SM, 7/SMSP) for latency hiding;
// launch_bounds(128,7) single wave (1024 CTAs <= 1036 slots); direct STG
// output from registers (quad-redundant lanes own tg-partitioned 128B
// sub-blocks) -- no smem staging, no syncwarp in the hot path.

#define BATCH 65536
#define TPB   128
#define WPB   4
#define TRAJW 16
#define GRID  (BATCH / (WPB * TRAJW))   // 1024 CTAs
#define NSEG  4

__device__ __forceinline__ uint32_t pack_bf16(float lo, float hi) {
    uint32_t d;
    asm("cvt.rn.bf16x2.f32 %0, %1, %2;" : "=r"(d) : "f"(hi), "f"(lo));
    return d;
}

__device__ __forceinline__ void mma_bf16(float c[4], const uint32_t a[4],
                                         const uint32_t b[2]) {
    asm volatile(
        "mma.sync.aligned.m16n8k16.row.col.f32.bf16.bf16.f32 "
        "{%0,%1,%2,%3}, {%4,%5,%6,%7}, {%8,%9}, {%0,%1,%2,%3};"
        : "+f"(c[0]), "+f"(c[1]), "+f"(c[2]), "+f"(c[3])
        : "r"(a[0]), "r"(a[1]), "r"(a[2]), "r"(a[3]), "r"(b[0]), "r"(b[1]));
}

__global__ __launch_bounds__(TPB, 7) void pk_node_mma(
    const float* __restrict__ y0,
    const float* __restrict__ W1, const float* __restrict__ b1,
    const float* __restrict__ W2, const float* __restrict__ b2,
    const float* __restrict__ W3, const float* __restrict__ b3,
    float* __restrict__ out)
{
    // B fragments for m16n8k16: [s(4)][nt(8)][lane(32)] x uint2 = 8KB.
    __shared__ __align__(16) uint32_t sB[4 * 8 * 32 * 2];
    __shared__ __align__(16) float4   sP1[64];   // {W1[0][c], W1[1][c], b1[c], 0}
    __shared__ __align__(16) float4   sP3[64];   // {b2[n], W3[n][0], W3[n][1], 0}
    __shared__ __align__(16) float4   sHerm[64]; // {h00,h10,h01,h11} per point

    const int tid  = threadIdx.x;
    const int lane = tid & 31;
    const int warp = tid >> 5;

    // ---- stage B = W2 in m16n8k16 .col fragment layout (bf16 pairs) ----
    for (int i = tid; i < 4 * 8 * 32; i += TPB) {
        int s = i >> 8, nt = (i >> 5) & 7, l = i & 31;
        int qq = l >> 2, tt = l & 3;
        int n  = 8 * nt + qq;
        int k0 = 16 * s + 2 * tt;
        sB[i * 2 + 0] = pack_bf16(W2[k0 * 64 + n],       W2[(k0 + 1) * 64 + n]);
        sB[i * 2 + 1] = pack_bf16(W2[(k0 + 8) * 64 + n], W2[(k0 + 9) * 64 + n]);
    }
    for (int i = tid; i < 64; i += TPB) {
        sP1[i] = make_float4(W1[i], W1[64 + i], b1[i], 0.f);
        sP3[i] = make_float4(b2[i], W3[2 * i], W3[2 * i + 1], 0.f);
        float th = (float)i * (1.0f / 63.0f);
        float t2 = th * th, t3 = t2 * th;
        sHerm[i] = make_float4(2.f * t3 - 3.f * t2 + 1.f,   // h00
                               t3 - 2.f * t2 + th,          // h10
                               -2.f * t3 + 3.f * t2,        // h01
                               t3 - t2);                    // h11
    }
    __syncthreads();

    const float b3a = b3[0], b3b = b3[1];
    const int q  = lane >> 2;   // fragment row/col group (0..7)
    const int tg = lane & 3;    // thread-in-group

    const int warpTraj = (blockIdx.x * WPB + warp) * TRAJW;

    // Trajectories q and q+8 (j = 0,1), redundant across the quad.
    float ya[2], yb[2];
#pragma unroll
    for (int j = 0; j < 2; j++) {
        float2 v = ((const float2*)y0)[warpTraj + q + 8 * j];
        ya[j] = v.x; yb[j] = v.y;
    }

    auto mlp = [&](const float xa[2], const float xb[2], float fa[2], float fb[2]) {
        // ---- Stage 1: A fragments for all 4 K-chunks (16 regs).
        uint32_t A0[4][4];
#pragma unroll
        for (int s = 0; s < 4; s++) {
            const int c0 = 16 * s + 2 * tg;
            float4 pA = sP1[c0],     pB = sP1[c0 + 1];
            float4 pC = sP1[c0 + 8], pD = sP1[c0 + 9];
            float hA0 = fmaxf(0.f, fmaf(xa[0], pA.x, fmaf(xb[0], pA.y, pA.z)));
            float hB0 = fmaxf(0.f, fmaf(xa[0], pB.x, fmaf(xb[0], pB.y, pB.z)));
            float hC0 = fmaxf(0.f, fmaf(xa[0], pC.x, fmaf(xb[0], pC.y, pC.z)));
            float hD0 = fmaxf(0.f, fmaf(xa[0], pD.x, fmaf(xb[0], pD.y, pD.z)));
            float hA1 = fmaxf(0.f, fmaf(xa[1], pA.x, fmaf(xb[1], pA.y, pA.z)));
            float hB1 = fmaxf(0.f, fmaf(xa[1], pB.x, fmaf(xb[1], pB.y, pB.z)));
            float hC1 = fmaxf(0.f, fmaf(xa[1], pC.x, fmaf(xb[1], pC.y, pC.z)));
            float hD1 = fmaxf(0.f, fmaf(xa[1], pD.x, fmaf(xb[1], pD.y, pD.z)));
            A0[s][0] = pack_bf16(hA0, hB0);   // row q,   k = c0, c0+1
            A0[s][1] = pack_bf16(hA1, hB1);   // row q+8
            A0[s][2] = pack_bf16(hC0, hD0);   // row q,   k = c0+8, c0+9
            A0[s][3] = pack_bf16(hC1, hD1);   // row q+8
        }

        // ---- Stage 2: per-nt 4-deep MMA chain + immediate layer-3 partial.
        float pa[2] = {0.f, 0.f}, pb[2] = {0.f, 0.f};
#pragma unroll
        for (int nt = 0; nt < 8; nt++) {
            float c0r[4] = {0.f, 0.f, 0.f, 0.f};
#pragma unroll
            for (int s = 0; s < 4; s++) {
                uint32_t bf[2];
                *(uint2*)bf = *(const uint2*)&sB[(((s << 3) | nt) << 5 | lane) * 2];
                mma_bf16(c0r, A0[s], bf);
            }
            const int n0 = 8 * nt + 2 * tg;
            float4 e0 = sP3[n0], e1 = sP3[n0 + 1];
            // rows: c0r[0,1] -> row q (cols n0, n0+1); c0r[2,3] -> row q+8.
            float h00 = fmaxf(0.f, c0r[0] + e0.x);
            float h01 = fmaxf(0.f, c0r[1] + e1.x);
            float h10 = fmaxf(0.f, c0r[2] + e0.x);
            float h11 = fmaxf(0.f, c0r[3] + e1.x);
            pa[0] = fmaf(h00, e0.y, fmaf(h01, e1.y, pa[0]));
            pb[0] = fmaf(h00, e0.z, fmaf(h01, e1.z, pb[0]));
            pa[1] = fmaf(h10, e0.y, fmaf(h11, e1.y, pa[1]));
            pb[1] = fmaf(h10, e0.z, fmaf(h11, e1.z, pb[1]));
        }
        // Quad butterfly reduce -> identical totals in all 4 lanes.
#pragma unroll
        for (int j = 0; j < 2; j++) {
            float sa = pa[j], sb = pb[j];
            sa += __shfl_xor_sync(0xffffffffu, sa, 1);
            sa += __shfl_xor_sync(0xffffffffu, sa, 2);
            sb += __shfl_xor_sync(0xffffffffu, sb, 1);
            sb += __shfl_xor_sync(0xffffffffu, sb, 2);
            fa[j] = b3a + sa;
            fb[j] = b3b + sb;
        }
    };

    const float h = 24.0f;

    for (int seg = 0; seg < NSEG; seg++) {
        // Heun: k1 = f(y); k2 = f(y + h k1); y1 = y + h/2 (k1 + k2).
        float k1a[2], k1b[2], ta[2], tb[2];
        mlp(ya, yb, k1a, k1b);

#pragma unroll
        for (int j = 0; j < 2; j++) {
            ta[j] = fmaf(24.f, k1a[j], ya[j]);   // Euler predictor
            tb[j] = fmaf(24.f, k1b[j], yb[j]);
        }
        float k2a[2], k2b[2];
        mlp(ta, tb, k2a, k2b);   // end slope -> Hermite

        float y1a[2], y1b[2];
#pragma unroll
        for (int j = 0; j < 2; j++) {
            y1a[j] = ya[j] + 12.f * (k1a[j] + k2a[j]);
            y1b[j] = yb[j] + 12.f * (k1b[j] + k2b[j]);
        }

        // Direct dense-output writeout: lane (q,tg) owns points
        // [16tg, 16tg+16) of trajectories q and q+8 -> 8 float4 STGs each.
        float* po0 = out + (size_t)(warpTraj + q) * 512 + seg * 128 + tg * 32;
        float* po1 = po0 + 8 * 512;   // trajectory q+8
#pragma unroll
        for (int i = 0; i < 8; i++) {
            float4 hb0 = sHerm[16 * tg + 2 * i];
            float4 hb1 = sHerm[16 * tg + 2 * i + 1];
            const float c100 = h * hb0.y, c110 = h * hb0.w;
            const float c101 = h * hb1.y, c111 = h * hb1.w;
            float4 v0, v1;
            v0.x = hb0.x * ya[0] + hb0.z * y1a[0] + c100 * k1a[0] + c110 * k2a[0];
            v0.y = hb0.x * yb[0] + hb0.z * y1b[0] + c100 * k1b[0] + c110 * k2b[0];
            v0.z = hb1.x * ya[0] + hb1.z * y1a[0] + c101 * k1a[0] + c111 * k2a[0];
            v0.w = hb1.x * yb[0] + hb1.z * y1b[0] + c101 * k1b[0] + c111 * k2b[0];
            v1.x = hb0.x * ya[1] + hb0.z * y1a[1] + c100 * k1a[1] + c110 * k2a[1];
            v1.y = hb0.x * yb[1] + hb0.z * y1b[1] + c100 * k1b[1] + c110 * k2b[1];
            v1.z = hb1.x * ya[1] + hb1.z * y1a[1] + c101 * k1a[1] + c111 * k2a[1];
            v1.w = hb1.x * yb[1] + hb1.z * y1b[1] + c101 * k1b[1] + c111 * k2b[1];
            *(float4*)(po0 + i * 4) = v0;
            *(float4*)(po1 + i * 4) = v1;
        }

        // Advance state; bolus dose into compartment 0 between segments.
#pragma unroll
        for (int j = 0; j < 2; j++) {
            ya[j] = (seg < NSEG - 1) ? y1a[j] + 100.0f : y1a[j];
            yb[j] = y1b[j];
        }
    }
}

extern "C" void kernel_launch(void* const* d_in, const int* in_sizes, int n_in,
                              void* d_out, int out_size)
{
    (void)in_sizes; (void)n_in; (void)out_size;
    pk_node_mma<<<GRID, TPB>>>(
        (const float*)d_in[0],
        (const float*)d_in[1], (const float*)d_in[2],
        (const float*)d_in[3], (const float*)d_in[4],
        (const float*)d_in[5], (const float*)d_in[6],
        (float*)d_out);
}

// round 15
// speedup vs baseline: 1.1345x; 1.1345x over previous
#include <cuda_runtime.h>
#include <cstdint>

// PKNeuralODE: 65536 trajectories, 2->64->64->2 ReLU MLP dynamics.
// One Heun step (h=24) per segment: k1=f(y), k2=f(y+h k1), y1=y+h/2(k1+k2).
// Dense output via cubic in Horner form with packed f32x2 FMA; coefficients
// built once per segment per trajectory. Direct STG.128 from registers.
// Layer 2 via mma.sync m16n8k16 bf16, nt-outer. R13 chassis: TPB=128,
// 4 warps/CTA, 32 traj/warp, launch_bounds(128,4) -> full 128-reg budget.

#define BATCH 65536
#define TPB   128
#define WPB   4
#define GRID  (BATCH / TPB)   // 512 CTAs, 4 warps each, 32 traj/warp
#define NSEG  4

__device__ __forceinline__ uint32_t pack_bf16(float lo, float hi) {
    uint32_t d;
    asm("cvt.rn.bf16x2.f32 %0, %1, %2;" : "=r"(d) : "f"(hi), "f"(lo));
    return d;
}

__device__ __forceinline__ void mma_bf16(float c[4], const uint32_t a[4],
                                         const uint32_t b[2]) {
    asm volatile(
        "mma.sync.aligned.m16n8k16.row.col.f32.bf16.bf16.f32 "
        "{%0,%1,%2,%3}, {%4,%5,%6,%7}, {%8,%9}, {%0,%1,%2,%3};"
        : "+f"(c[0]), "+f"(c[1]), "+f"(c[2]), "+f"(c[3])
        : "r"(a[0]), "r"(a[1]), "r"(a[2]), "r"(a[3]), "r"(b[0]), "r"(b[1]));
}

__device__ __forceinline__ uint64_t pack_f32x2(float lo, float hi) {
    uint64_t d;
    asm("mov.b64 %0, {%1, %2};" : "=l"(d) : "f"(lo), "f"(hi));
    return d;
}
__device__ __forceinline__ uint64_t fma_f32x2(uint64_t a, uint64_t b, uint64_t c) {
    uint64_t d;
    asm("fma.rn.f32x2 %0, %1, %2, %3;" : "=l"(d) : "l"(a), "l"(b), "l"(c));
    return d;
}

__global__ __launch_bounds__(TPB, 4) void pk_node_mma(
    const float* __restrict__ y0,
    const float* __restrict__ W1, const float* __restrict__ b1,
    const float* __restrict__ W2, const float* __restrict__ b2,
    const float* __restrict__ W3, const float* __restrict__ b3,
    float* __restrict__ out)
{
    // B fragments for m16n8k16: [s(4)][nt(8)][lane(32)] x uint2 = 8KB.
    __shared__ __align__(16) uint32_t sB[4 * 8 * 32 * 2];
    __shared__ __align__(16) float4   sP1[64];   // {W1[0][c], W1[1][c], b1[c], 0}
    __shared__ __align__(16) float4   sP3[64];   // {b2[n], W3[n][0], W3[n][1], 0}

    const int tid  = threadIdx.x;
    const int lane = tid & 31;
    const int warp = tid >> 5;

    // ---- stage B = W2 in m16n8k16 .col fragment layout (bf16 pairs) ----
    for (int i = tid; i < 4 * 8 * 32; i += TPB) {
        int s = i >> 8, nt = (i >> 5) & 7, l = i & 31;
        int qq = l >> 2, tt = l & 3;
        int n  = 8 * nt + qq;
        int k0 = 16 * s + 2 * tt;
        sB[i * 2 + 0] = pack_bf16(W2[k0 * 64 + n],       W2[(k0 + 1) * 64 + n]);
        sB[i * 2 + 1] = pack_bf16(W2[(k0 + 8) * 64 + n], W2[(k0 + 9) * 64 + n]);
    }
    for (int i = tid; i < 64; i += TPB) {
        sP1[i] = make_float4(W1[i], W1[64 + i], b1[i], 0.f);
        sP3[i] = make_float4(b2[i], W3[2 * i], W3[2 * i + 1], 0.f);
    }
    __syncthreads();

    const float b3a = b3[0], b3b = b3[1];
    const int q  = lane >> 2;   // fragment row/col group (0..7)
    const int tg = lane & 3;    // thread-in-group

    const int warpTraj = (blockIdx.x * WPB + warp) * 32;

    // Trajectories q + 8j (j=0..3), redundant across the quad.
    float ya[4], yb[4];
#pragma unroll
    for (int j = 0; j < 4; j++) {
        float2 v = ((const float2*)y0)[warpTraj + q + 8 * j];
        ya[j] = v.x; yb[j] = v.y;
    }

    auto mlp = [&](const float xa[4], const float xb[4], float fa[4], float fb[4]) {
        // ---- Stage 1: A fragments for all 4 K-chunks (32 transient regs).
        uint32_t A0[4][4], A1[4][4];
#pragma unroll
        for (int s = 0; s < 4; s++) {
            const int c0 = 16 * s + 2 * tg;
            float4 pA = sP1[c0],     pB = sP1[c0 + 1];
            float4 pC = sP1[c0 + 8], pD = sP1[c0 + 9];
#pragma unroll
            for (int mt = 0; mt < 2; mt++) {
                const int j0 = 2 * mt, j1 = 2 * mt + 1;   // rows q+8*j0, q+8*j1
                uint32_t* A = mt ? A1[s] : A0[s];
                float hA0 = fmaxf(0.f, fmaf(xa[j0], pA.x, fmaf(xb[j0], pA.y, pA.z)));
                float hB0 = fmaxf(0.f, fmaf(xa[j0], pB.x, fmaf(xb[j0], pB.y, pB.z)));
                float hC0 = fmaxf(0.f, fmaf(xa[j0], pC.x, fmaf(xb[j0], pC.y, pC.z)));
                float hD0 = fmaxf(0.f, fmaf(xa[j0], pD.x, fmaf(xb[j0], pD.y, pD.z)));
                float hA1 = fmaxf(0.f, fmaf(xa[j1], pA.x, fmaf(xb[j1], pA.y, pA.z)));
                float hB1 = fmaxf(0.f, fmaf(xa[j1], pB.x, fmaf(xb[j1], pB.y, pB.z)));
                float hC1 = fmaxf(0.f, fmaf(xa[j1], pC.x, fmaf(xb[j1], pC.y, pC.z)));
                float hD1 = fmaxf(0.f, fmaf(xa[j1], pD.x, fmaf(xb[j1], pD.y, pD.z)));
                A[0] = pack_bf16(hA0, hB0);
                A[1] = pack_bf16(hA1, hB1);
                A[2] = pack_bf16(hC0, hD0);
                A[3] = pack_bf16(hC1, hD1);
            }
        }

        // ---- Stage 2: per-nt 4-deep MMA chain + immediate layer-3 partial.
        float pa[4][2], pb[4][2];
#pragma unroll
        for (int j = 0; j < 4; j++) {
            pa[j][0] = pa[j][1] = 0.f;
            pb[j][0] = pb[j][1] = 0.f;
        }
#pragma unroll
        for (int nt = 0; nt < 8; nt++) {
            float c0[4] = {0.f, 0.f, 0.f, 0.f};
            float c1[4] = {0.f, 0.f, 0.f, 0.f};
#pragma unroll
            for (int s = 0; s < 4; s++) {
                uint32_t bf[2];
                *(uint2*)bf = *(const uint2*)&sB[(((s << 3) | nt) << 5 | lane) * 2];
                mma_bf16(c0, A0[s], bf);
                mma_bf16(c1, A1[s], bf);
            }
            const int par = nt & 1;
            const int n0 = 8 * nt + 2 * tg;
            float4 e0 = sP3[n0], e1 = sP3[n0 + 1];
            // rows: c0 -> j=0 (q), j=1 (q+8); c1 -> j=2 (q+16), j=3 (q+24)
            float h00 = fmaxf(0.f, c0[0] + e0.x);
            float h01 = fmaxf(0.f, c0[1] + e1.x);
            float h10 = fmaxf(0.f, c0[2] + e0.x);
            float h11 = fmaxf(0.f, c0[3] + e1.x);
            pa[0][par] = fmaf(h00, e0.y, fmaf(h01, e1.y, pa[0][par]));
            pb[0][par] = fmaf(h00, e0.z, fmaf(h01, e1.z, pb[0][par]));
            pa[1][par] = fmaf(h10, e0.y, fmaf(h11, e1.y, pa[1][par]));
            pb[1][par] = fmaf(h10, e0.z, fmaf(h11, e1.z, pb[1][par]));
            float g00 = fmaxf(0.f, c1[0] + e0.x);
            float g01 = fmaxf(0.f, c1[1] + e1.x);
            float g10 = fmaxf(0.f, c1[2] + e0.x);
            float g11 = fmaxf(0.f, c1[3] + e1.x);
            pa[2][par] = fmaf(g00, e0.y, fmaf(g01, e1.y, pa[2][par]));
            pb[2][par] = fmaf(g00, e0.z, fmaf(g01, e1.z, pb[2][par]));
            pa[3][par] = fmaf(g10, e0.y, fmaf(g11, e1.y, pa[3][par]));
            pb[3][par] = fmaf(g10, e0.z, fmaf(g11, e1.z, pb[3][par]));
        }
        // Quad butterfly reduce -> identical totals in all 4 lanes.
#pragma unroll
        for (int j = 0; j < 4; j++) {
            float sa = pa[j][0] + pa[j][1];
            float sb = pb[j][0] + pb[j][1];
            sa += __shfl_xor_sync(0xffffffffu, sa, 1);
            sa += __shfl_xor_sync(0xffffffffu, sa, 2);
            sb += __shfl_xor_sync(0xffffffffu, sb, 1);
            sb += __shfl_xor_sync(0xffffffffu, sb, 2);
            fa[j] = b3a + sa;
            fb[j] = b3b + sb;
        }
    };

    const float thbase = (float)tg * (16.0f / 63.0f);

    for (int seg = 0; seg < NSEG; seg++) {
        // Heun: k1 = f(y); k2 = f(y + h k1); y1 = y + h/2 (k1 + k2).
        float k1a[4], k1b[4], ta[4], tb[4];
        mlp(ya, yb, k1a, k1b);

#pragma unroll
        for (int j = 0; j < 4; j++) {
            ta[j] = fmaf(24.f, k1a[j], ya[j]);   // Euler predictor
            tb[j] = fmaf(24.f, k1b[j], yb[j]);
        }
        float k2a[4], k2b[4];
        mlp(ta, tb, k2a, k2b);   // end slope

        float y1a[4], y1b[4];
#pragma unroll
        for (int j = 0; j < 4; j++) {
            y1a[j] = ya[j] + 12.f * (k1a[j] + k2a[j]);
            y1b[j] = yb[j] + 12.f * (k1b[j] + k2b[j]);
        }

        // Cubic dense output, Horner form, packed f32x2 over (a,b):
        //   val(t) = c0 + t(c1 + t(c2 + t c3)),  t = point/63
        //   c0=y0, c1=Hk1, c2=3(y1-y0)-2Hk1-Hk2, c3=Hk1+Hk2-2(y1-y0), H=24.
        uint64_t C0[4], C1[4], C2[4], C3[4];
#pragma unroll
        for (int j = 0; j < 4; j++) {
            float dya = y1a[j] - ya[j],  dyb = y1b[j] - yb[j];
            float g1a = 24.f * k1a[j],   g1b = 24.f * k1b[j];
            float g2a = 24.f * k2a[j],   g2b = 24.f * k2b[j];
            float c2a = fmaf(3.f, dya, -2.f * g1a - g2a);
            float c2b = fmaf(3.f, dyb, -2.f * g1b - g2b);
            float c3a = g1a + g2a - 2.f * dya;
            float c3b = g1b + g2b - 2.f * dyb;
            C0[j] = pack_f32x2(ya[j], yb[j]);
            C1[j] = pack_f32x2(g1a, g1b);
            C2[j] = pack_f32x2(c2a, c2b);
            C3[j] = pack_f32x2(c3a, c3b);
        }

        // Lane (q,tg) writes points [16tg, 16tg+16) of traj q+8j.
        float* po = out + (size_t)(warpTraj + q) * 512 + seg * 128 + 32 * tg;
#pragma unroll
        for (int i = 0; i < 16; i += 2) {
            float t0 = fmaf((float)i,     1.0f / 63.0f, thbase);
            float t1 = fmaf((float)(i+1), 1.0f / 63.0f, thbase);
            uint64_t T0 = pack_f32x2(t0, t0);
            uint64_t T1 = pack_f32x2(t1, t1);
#pragma unroll
            for (int j = 0; j < 4; j++) {
                uint64_t v0 = fma_f32x2(T0,
                                fma_f32x2(T0, fma_f32x2(T0, C3[j], C2[j]), C1[j]),
                                C0[j]);
                uint64_t v1 = fma_f32x2(T1,
                                fma_f32x2(T1, fma_f32x2(T1, C3[j], C2[j]), C1[j]),
                                C0[j]);
                uint2 u0 = *(uint2*)&v0, u1 = *(uint2*)&v1;
                uint4 w = make_uint4(u0.x, u0.y, u1.x, u1.y);
                *(uint4*)(po + (size_t)j * 8 * 512 + 2 * i) = w;
            }
        }

        // Advance state; bolus dose into compartment 0 between segments.
#pragma unroll
        for (int j = 0; j < 4; j++) {
            ya[j] = (seg < NSEG - 1) ? y1a[j] + 100.0f : y1a[j];
            yb[j] = y1b[j];
        }
    }
}

extern "C" void kernel_launch(void* const* d_in, const int* in_sizes, int n_in,
                              void* d_out, int out_size)
{
    (void)in_sizes; (void)n_in; (void)out_size;
    pk_node_mma<<<GRID, TPB>>>(
        (const float*)d_in[0],
        (const float*)d_in[1], (const float*)d_in[2],
        (const float*)d_in[3], (const float*)d_in[4],
        (const float*)d_in[5], (const float*)d_in[6],
        (float*)d_out);
}

// round 16
// speedup vs baseline: 1.9834x; 1.7482x over previous
#include <cuda_runtime.h>
#include <cstdint>

// PKNeuralODE: 65536 trajectories, 2->64->64->2 ReLU MLP dynamics.
// One Heun step (h=24) per segment: k1=f(y), k2=f(y+h k1), y1=y+h/2(k1+k2).
// Dense output: cubic in Horner form with packed f32x2 FMA (coefficients once
// per segment), staged in smem, written as full 128B coalesced lines (the
// staged writeout is load-bearing: direct scattered STG cost 2x in R14/R15).
// Layer 2 via mma.sync m16n8k16 bf16, nt-outer. R13 chassis: TPB=128,
// 4 warps/CTA, 32 traj/warp, launch_bounds(128,4) -> full 128-reg budget.

#define BATCH 65536
#define TPB   128
#define WPB   4
#define GRID  (BATCH / TPB)   // 512 CTAs, 4 warps each, 32 traj/warp
#define NSEG  4
#define ROWF  36

__device__ __forceinline__ uint32_t pack_bf16(float lo, float hi) {
    uint32_t d;
    asm("cvt.rn.bf16x2.f32 %0, %1, %2;" : "=r"(d) : "f"(hi), "f"(lo));
    return d;
}

__device__ __forceinline__ void mma_bf16(float c[4], const uint32_t a[4],
                                         const uint32_t b[2]) {
    asm volatile(
        "mma.sync.aligned.m16n8k16.row.col.f32.bf16.bf16.f32 "
        "{%0,%1,%2,%3}, {%4,%5,%6,%7}, {%8,%9}, {%0,%1,%2,%3};"
        : "+f"(c[0]), "+f"(c[1]), "+f"(c[2]), "+f"(c[3])
        : "r"(a[0]), "r"(a[1]), "r"(a[2]), "r"(a[3]), "r"(b[0]), "r"(b[1]));
}

__device__ __forceinline__ uint64_t pack_f32x2(float lo, float hi) {
    uint64_t d;
    asm("mov.b64 %0, {%1, %2};" : "=l"(d) : "f"(lo), "f"(hi));
    return d;
}
__device__ __forceinline__ uint64_t fma_f32x2(uint64_t a, uint64_t b, uint64_t c) {
    uint64_t d;
    asm("fma.rn.f32x2 %0, %1, %2, %3;" : "=l"(d) : "l"(a), "l"(b), "l"(c));
    return d;
}

__global__ __launch_bounds__(TPB, 4) void pk_node_mma(
    const float* __restrict__ y0,
    const float* __restrict__ W1, const float* __restrict__ b1,
    const float* __restrict__ W2, const float* __restrict__ b2,
    const float* __restrict__ W3, const float* __restrict__ b3,
    float* __restrict__ out)
{
    // B fragments for m16n8k16: [s(4)][nt(8)][lane(32)] x uint2 = 8KB.
    __shared__ __align__(16) uint32_t sB[4 * 8 * 32 * 2];
    __shared__ __align__(16) float4   sP1[64];   // {W1[0][c], W1[1][c], b1[c], 0}
    __shared__ __align__(16) float4   sP3[64];   // {b2[n], W3[n][0], W3[n][1], 0}
    __shared__ __align__(16) float    sOut[WPB][32][ROWF];  // per-warp staging

    const int tid  = threadIdx.x;
    const int lane = tid & 31;
    const int warp = tid >> 5;

    // ---- stage B = W2 in m16n8k16 .col fragment layout (bf16 pairs) ----
    for (int i = tid; i < 4 * 8 * 32; i += TPB) {
        int s = i >> 8, nt = (i >> 5) & 7, l = i & 31;
        int qq = l >> 2, tt = l & 3;
        int n  = 8 * nt + qq;
        int k0 = 16 * s + 2 * tt;
        sB[i * 2 + 0] = pack_bf16(W2[k0 * 64 + n],       W2[(k0 + 1) * 64 + n]);
        sB[i * 2 + 1] = pack_bf16(W2[(k0 + 8) * 64 + n], W2[(k0 + 9) * 64 + n]);
    }
    for (int i = tid; i < 64; i += TPB) {
        sP1[i] = make_float4(W1[i], W1[64 + i], b1[i], 0.f);
        sP3[i] = make_float4(b2[i], W3[2 * i], W3[2 * i + 1], 0.f);
    }
    __syncthreads();

    const float b3a = b3[0], b3b = b3[1];
    const int q  = lane >> 2;   // fragment row/col group (0..7)
    const int tg = lane & 3;    // thread-in-group

    const int warpTraj = (blockIdx.x * WPB + warp) * 32;

    // Trajectories q + 8j (j=0..3), redundant across the quad.
    float ya[4], yb[4];
#pragma unroll
    for (int j = 0; j < 4; j++) {
        float2 v = ((const float2*)y0)[warpTraj + q + 8 * j];
        ya[j] = v.x; yb[j] = v.y;
    }

    auto mlp = [&](const float xa[4], const float xb[4], float fa[4], float fb[4]) {
        // ---- Stage 1: A fragments for all 4 K-chunks (32 transient regs).
        uint32_t A0[4][4], A1[4][4];
#pragma unroll
        for (int s = 0; s < 4; s++) {
            const int c0 = 16 * s + 2 * tg;
            float4 pA = sP1[c0],     pB = sP1[c0 + 1];
            float4 pC = sP1[c0 + 8], pD = sP1[c0 + 9];
#pragma unroll
            for (int mt = 0; mt < 2; mt++) {
                const int j0 = 2 * mt, j1 = 2 * mt + 1;   // rows q+8*j0, q+8*j1
                uint32_t* A = mt ? A1[s] : A0[s];
                float hA0 = fmaxf(0.f, fmaf(xa[j0], pA.x, fmaf(xb[j0], pA.y, pA.z)));
                float hB0 = fmaxf(0.f, fmaf(xa[j0], pB.x, fmaf(xb[j0], pB.y, pB.z)));
                float hC0 = fmaxf(0.f, fmaf(xa[j0], pC.x, fmaf(xb[j0], pC.y, pC.z)));
                float hD0 = fmaxf(0.f, fmaf(xa[j0], pD.x, fmaf(xb[j0], pD.y, pD.z)));
                float hA1 = fmaxf(0.f, fmaf(xa[j1], pA.x, fmaf(xb[j1], pA.y, pA.z)));
                float hB1 = fmaxf(0.f, fmaf(xa[j1], pB.x, fmaf(xb[j1], pB.y, pB.z)));
                float hC1 = fmaxf(0.f, fmaf(xa[j1], pC.x, fmaf(xb[j1], pC.y, pC.z)));
                float hD1 = fmaxf(0.f, fmaf(xa[j1], pD.x, fmaf(xb[j1], pD.y, pD.z)));
                A[0] = pack_bf16(hA0, hB0);
                A[1] = pack_bf16(hA1, hB1);
                A[2] = pack_bf16(hC0, hD0);
                A[3] = pack_bf16(hC1, hD1);
            }
        }

        // ---- Stage 2: per-nt 4-deep MMA chain + immediate layer-3 partial.
        float pa[4][2], pb[4][2];
#pragma unroll
        for (int j = 0; j < 4; j++) {
            pa[j][0] = pa[j][1] = 0.f;
            pb[j][0] = pb[j][1] = 0.f;
        }
#pragma unroll
        for (int nt = 0; nt < 8; nt++) {
            float c0[4] = {0.f, 0.f, 0.f, 0.f};
            float c1[4] = {0.f, 0.f, 0.f, 0.f};
#pragma unroll
            for (int s = 0; s < 4; s++) {
                uint32_t bf[2];
                *(uint2*)bf = *(const uint2*)&sB[(((s << 3) | nt) << 5 | lane) * 2];
                mma_bf16(c0, A0[s], bf);
                mma_bf16(c1, A1[s], bf);
            }
            const int par = nt & 1;
            const int n0 = 8 * nt + 2 * tg;
            float4 e0 = sP3[n0], e1 = sP3[n0 + 1];
            // rows: c0 -> j=0 (q), j=1 (q+8); c1 -> j=2 (q+16), j=3 (q+24)
            float h00 = fmaxf(0.f, c0[0] + e0.x);
            float h01 = fmaxf(0.f, c0[1] + e1.x);
            float h10 = fmaxf(0.f, c0[2] + e0.x);
            float h11 = fmaxf(0.f, c0[3] + e1.x);
            pa[0][par] = fmaf(h00, e0.y, fmaf(h01, e1.y, pa[0][par]));
            pb[0][par] = fmaf(h00, e0.z, fmaf(h01, e1.z, pb[0][par]));
            pa[1][par] = fmaf(h10, e0.y, fmaf(h11, e1.y, pa[1][par]));
            pb[1][par] = fmaf(h10, e0.z, fmaf(h11, e1.z, pb[1][par]));
            float g00 = fmaxf(0.f, c1[0] + e0.x);
            float g01 = fmaxf(0.f, c1[1] + e1.x);
            float g10 = fmaxf(0.f, c1[2] + e0.x);
            float g11 = fmaxf(0.f, c1[3] + e1.x);
            pa[2][par] = fmaf(g00, e0.y, fmaf(g01, e1.y, pa[2][par]));
            pb[2][par] = fmaf(g00, e0.z, fmaf(g01, e1.z, pb[2][par]));
            pa[3][par] = fmaf(g10, e0.y, fmaf(g11, e1.y, pa[3][par]));
            pb[3][par] = fmaf(g10, e0.z, fmaf(g11, e1.z, pb[3][par]));
        }
        // Quad butterfly reduce -> identical totals in all 4 lanes.
#pragma unroll
        for (int j = 0; j < 4; j++) {
            float sa = pa[j][0] + pa[j][1];
            float sb = pb[j][0] + pb[j][1];
            sa += __shfl_xor_sync(0xffffffffu, sa, 1);
            sa += __shfl_xor_sync(0xffffffffu, sa, 2);
            sb += __shfl_xor_sync(0xffffffffu, sb, 1);
            sb += __shfl_xor_sync(0xffffffffu, sb, 2);
            fa[j] = b3a + sa;
            fb[j] = b3b + sb;
        }
    };

    float (*buf)[ROWF] = sOut[warp];

    for (int seg = 0; seg < NSEG; seg++) {
        // Heun: k1 = f(y); k2 = f(y + h k1); y1 = y + h/2 (k1 + k2).
        float k1a[4], k1b[4], ta[4], tb[4];
        mlp(ya, yb, k1a, k1b);

#pragma unroll
        for (int j = 0; j < 4; j++) {
            ta[j] = fmaf(24.f, k1a[j], ya[j]);   // Euler predictor
            tb[j] = fmaf(24.f, k1b[j], yb[j]);
        }
        float k2a[4], k2b[4];
        mlp(ta, tb, k2a, k2b);   // end slope

        float y1a[4], y1b[4];
#pragma unroll
        for (int j = 0; j < 4; j++) {
            y1a[j] = ya[j] + 12.f * (k1a[j] + k2a[j]);
            y1b[j] = yb[j] + 12.f * (k1b[j] + k2b[j]);
        }

        // Cubic dense output, Horner form, packed f32x2 over (a,b):
        //   val(t) = c0 + t(c1 + t(c2 + t c3)),  t = point/63
        //   c0=y0, c1=Hk1, c2=3(y1-y0)-2Hk1-Hk2, c3=Hk1+Hk2-2(y1-y0), H=24.
        uint64_t C0[4], C1[4], C2[4], C3[4];
#pragma unroll
        for (int j = 0; j < 4; j++) {
            float dya = y1a[j] - ya[j],  dyb = y1b[j] - yb[j];
            float g1a = 24.f * k1a[j],   g1b = 24.f * k1b[j];
            float g2a = 24.f * k2a[j],   g2b = 24.f * k2b[j];
            float c2a = fmaf(3.f, dya, -2.f * g1a - g2a);
            float c2b = fmaf(3.f, dyb, -2.f * g1b - g2b);
            float c3a = g1a + g2a - 2.f * dya;
            float c3b = g1b + g2b - 2.f * dyb;
            C0[j] = pack_f32x2(ya[j], yb[j]);
            C1[j] = pack_f32x2(g1a, g1b);
            C2[j] = pack_f32x2(c2a, c2b);
            C3[j] = pack_f32x2(c3a, c3b);
        }

        // Dense output: 64 points, 4 chunks of 16; quad splits points by tg.
#pragma unroll
        for (int ch = 0; ch < 4; ch++) {
#pragma unroll
            for (int i = 0; i < 4; i++) {
                const int p = 4 * i + tg;           // point within chunk
                const float t = (float)(ch * 16 + p) * (1.0f / 63.0f);
                uint64_t T = pack_f32x2(t, t);
#pragma unroll
                for (int j = 0; j < 4; j++) {
                    uint64_t v = fma_f32x2(T,
                                   fma_f32x2(T, fma_f32x2(T, C3[j], C2[j]), C1[j]),
                                   C0[j]);
                    *(uint64_t*)&buf[q + 8 * j][2 * p] = v;
                }
            }
            __syncwarp();
            // Coalesced writeout: 8 lanes x float4 = 128B line per trajectory.
#pragma unroll
            for (int it = 0; it < 8; it++) {
                int tr = it * 4 + (lane >> 3);
                int li = lane & 7;
                float4 v = *(float4*)&buf[tr][li * 4];
                *(float4*)(out + (size_t)(warpTraj + tr) * 512
                               + seg * 128 + ch * 32 + li * 4) = v;
            }
            __syncwarp();
        }

        // Advance state; bolus dose into compartment 0 between segments.
#pragma unroll
        for (int j = 0; j < 4; j++) {
            ya[j] = (seg < NSEG - 1) ? y1a[j] + 100.0f : y1a[j];
            yb[j] = y1b[j];
        }
    }
}

extern "C" void kernel_launch(void* const* d_in, const int* in_sizes, int n_in,
                              void* d_out, int out_size)
{
    (void)in_sizes; (void)n_in; (void)out_size;
    pk_node_mma<<<GRID, TPB>>>(
        (const float*)d_in[0],
        (const float*)d_in[1], (const float*)d_in[2],
        (const float*)d_in[3], (const float*)d_in[4],
        (const float*)d_in[5], (const float*)d_in[6],
        (float*)d_out);
}